// round 11
// baseline (speedup 1.0000x reference)
#include <cuda_runtime.h>
#include <cuda_bf16.h>
#include <math.h>

#define BB 64
#define CC 512
#define KK 64
#define HW 4096
#define NSPLIT 8          // = q splits (8)

#define AST 20            // A staging row stride (u32)
#define BST 136           // big tile row stride (u32): 256 cpair rows x 128 cols

// dynamic smem layout (bytes)
#define OFF_T    0                    // big tile: 256*136*4 = 139264
#define OFF_W    139264               // W / Av staging: 2*64*20*4 = 10240
#define OFF_X    149504               // scratch: ssq / colmax / colsum / Avs (24576)
#define OFF_RN   174080               // rnorm_s: 512
#define OFF_BIAS 174592               // bias: 256
#define SMEM_TOTAL 174848

// ---- scratch (device globals; no allocation allowed) ----
__device__ __align__(16) __nv_bfloat16 g_wb[KK * CC];
__device__ __align__(16) __nv_bfloat16 g_Av[(size_t)BB * 8 * KK * 512];  // [b][q][k][c]
__device__ __align__(16) float         g_asum_part[BB * KK * 32];
__device__ __align__(16) float         g_vpart[(size_t)NSPLIT * BB * KK * CC];
__device__ __align__(16) float         g_gss[BB * KK];
__device__ int g_flag[BB];

__device__ __forceinline__ void mma16816(float* d, const unsigned* a, const unsigned* b) {
    asm volatile(
        "mma.sync.aligned.m16n8k16.row.col.f32.bf16.bf16.f32 "
        "{%0,%1,%2,%3}, {%4,%5,%6,%7}, {%8,%9}, {%0,%1,%2,%3};"
        : "+f"(d[0]), "+f"(d[1]), "+f"(d[2]), "+f"(d[3])
        : "r"(a[0]), "r"(a[1]), "r"(a[2]), "r"(a[3]), "r"(b[0]), "r"(b[1]));
}

__device__ __forceinline__ unsigned pack_bf2(float lo, float hi) {
    __nv_bfloat162 p = __floats2bfloat162_rn(lo, hi);
    return *reinterpret_cast<unsigned*>(&p);
}
__device__ __forceinline__ unsigned short bf16bits(float v) {
    __nv_bfloat16 h = __float2bfloat16(v);
    return *reinterpret_cast<unsigned short*>(&h);
}
__device__ __forceinline__ void cpasync16(void* smem, const void* gmem) {
    unsigned s = (unsigned)__cvta_generic_to_shared(smem);
    asm volatile("cp.async.ca.shared.global [%0], [%1], 16;\n" :: "r"(s), "l"(gmem));
}
__device__ __forceinline__ void cp_commit() { asm volatile("cp.async.commit_group;\n"); }
__device__ __forceinline__ void cp_wait0()  { asm volatile("cp.async.wait_group 0;\n"); }

// ---------------- K_pre: convert weights + reset flags ----------------
__global__ void k_pre(const float* __restrict__ w) {
    int t = blockIdx.x * 256 + threadIdx.x;
    if (t < KK * CC) g_wb[t] = __float2bfloat16(w[t]);
    if (blockIdx.x == 0 && threadIdx.x < BB) g_flag[threadIdx.x] = 0;
}

// ---------------- K_main: one block = one (b, i-tile); phase1 logits, phase2 vlad ----
__global__ __launch_bounds__(512, 1) void k_main(const float* __restrict__ x,
                                                 const float* __restrict__ conv_b) {
    extern __shared__ __align__(16) char sm[];
    unsigned* T   = reinterpret_cast<unsigned*>(sm + OFF_T);
    unsigned* smW = reinterpret_cast<unsigned*>(sm + OFF_W);
    float* rnorm_s = reinterpret_cast<float*>(sm + OFF_RN);
    float* bias_s  = reinterpret_cast<float*>(sm + OFF_BIAS);

    const int bid = blockIdx.x;
    const int b  = bid >> 5;
    const int tt = bid & 31;          // tile within batch
    const int i0 = tt * 128;
    const int qq = tt >> 2;           // i0 >> 9
    const int r4 = tt & 3;            // c2-range index
    const int t  = threadIdx.x;
    const int lane = t & 31, warp = t >> 5;
    const int mw = warp >> 2, nw = warp & 3;   // 4x4 warp tiling (m64 x n128)
    const int g = lane >> 2, tg = lane & 3;
    const int row = mw * 16 + g;

    if (t < KK) bias_s[t] = conv_b[t];

    const float* xb = x + (size_t)b * CC * HW + i0;
    const unsigned* wb32 = reinterpret_cast<const unsigned*>(g_wb);
    const int c4 = t & 31, cg = t >> 5;        // x loader: 4 cols, 2 channels

    float acc[4][4];
#pragma unroll
    for (int nt = 0; nt < 4; nt++)
#pragma unroll
        for (int qd = 0; qd < 4; qd++) acc[nt][qd] = 0.f;
    float4 ssq4 = make_float4(0.f, 0.f, 0.f, 0.f);

    // ================= PHASE 1: logits GEMM (K = c, streamed into persistent tile T) =====
    float4 xa0, xa1;
    if (t < 256)
        cpasync16(smW + (t >> 2) * AST + (t & 3) * 4,
                  wb32 + (t >> 2) * (CC / 2) + (t & 3) * 4);
    cp_commit();
    xa0 = *reinterpret_cast<const float4*>(xb + (size_t)(2 * cg) * HW + c4 * 4);
    xa1 = *reinterpret_cast<const float4*>(xb + (size_t)(2 * cg + 1) * HW + c4 * 4);
    {
        ssq4.x += xa0.x * xa0.x + xa1.x * xa1.x;
        ssq4.y += xa0.y * xa0.y + xa1.y * xa1.y;
        ssq4.z += xa0.z * xa0.z + xa1.z * xa1.z;
        ssq4.w += xa0.w * xa0.w + xa1.w * xa1.w;
        uint4 p = make_uint4(pack_bf2(xa0.x, xa1.x), pack_bf2(xa0.y, xa1.y),
                             pack_bf2(xa0.z, xa1.z), pack_bf2(xa0.w, xa1.w));
        *reinterpret_cast<uint4*>(T + cg * BST + c4 * 4) = p;
    }
    cp_wait0();
    __syncthreads();

    for (int it = 0; it < 16; it++) {
        const int c1 = (it + 1) * 32;
        const int s = it & 1, sn = s ^ 1;
        if (it < 15) {
            if (t < 256)
                cpasync16(smW + sn * (KK * AST) + (t >> 2) * AST + (t & 3) * 4,
                          wb32 + (t >> 2) * (CC / 2) + (c1 >> 1) + (t & 3) * 4);
            xa0 = *reinterpret_cast<const float4*>(xb + (size_t)(c1 + 2 * cg) * HW + c4 * 4);
            xa1 = *reinterpret_cast<const float4*>(xb + (size_t)(c1 + 2 * cg + 1) * HW + c4 * 4);
        }
        cp_commit();

        const unsigned* Ws = smW + s * (KK * AST);
        const int rbase = it * 16;
#pragma unroll
        for (int ks = 0; ks < 2; ks++) {
            unsigned a[4];
            a[0] = Ws[row * AST + ks * 8 + tg];
            a[1] = Ws[(row + 8) * AST + ks * 8 + tg];
            a[2] = Ws[row * AST + ks * 8 + tg + 4];
            a[3] = Ws[(row + 8) * AST + ks * 8 + tg + 4];
#pragma unroll
            for (int nt = 0; nt < 4; nt++) {
                const int col = nw * 32 + nt * 8 + g;
                unsigned bf[2];
                bf[0] = T[(rbase + ks * 8 + tg) * BST + col];
                bf[1] = T[(rbase + ks * 8 + tg + 4) * BST + col];
                mma16816(acc[nt], a, bf);
            }
        }

        if (it < 15) {
            ssq4.x += xa0.x * xa0.x + xa1.x * xa1.x;
            ssq4.y += xa0.y * xa0.y + xa1.y * xa1.y;
            ssq4.z += xa0.z * xa0.z + xa1.z * xa1.z;
            ssq4.w += xa0.w * xa0.w + xa1.w * xa1.w;
            uint4 p = make_uint4(pack_bf2(xa0.x, xa1.x), pack_bf2(xa0.y, xa1.y),
                                 pack_bf2(xa0.z, xa1.z), pack_bf2(xa0.w, xa1.w));
            *reinterpret_cast<uint4*>(T + ((c1 >> 1) + cg) * BST + c4 * 4) = p;
        }
        cp_wait0();
        __syncthreads();
    }

    // ---- ssq -> rnorm (columns of this tile) ----
    {
        float4* ssq_sm = reinterpret_cast<float4*>(sm + OFF_X);   // [16][32]
        ssq_sm[cg * 32 + c4] = ssq4;
        __syncthreads();
        if (t < 32) {
            float4 s = ssq_sm[t];
#pragma unroll
            for (int r = 1; r < 16; r++) {
                float4 u = ssq_sm[r * 32 + t];
                s.x += u.x; s.y += u.y; s.z += u.z; s.w += u.w;
            }
            float4 rn;
            rn.x = 1.f / fmaxf(sqrtf(s.x), 1e-12f);
            rn.y = 1.f / fmaxf(sqrtf(s.y), 1e-12f);
            rn.z = 1.f / fmaxf(sqrtf(s.z), 1e-12f);
            rn.w = 1.f / fmaxf(sqrtf(s.w), 1e-12f);
            reinterpret_cast<float4*>(rnorm_s)[t] = rn;
        }
        __syncthreads();
    }

    float* colmax4 = reinterpret_cast<float*>(sm + OFF_X + 8192);   // [128][4]
    float* colsum4 = reinterpret_cast<float*>(sm + OFF_X + 10240);  // [128][4]
    float* asumW   = reinterpret_cast<float*>(sm + OFF_W);          // [64][4]

    const float b0v = bias_s[row], b1v = bias_s[row + 8];
#pragma unroll
    for (int nt = 0; nt < 4; nt++) {
        const int col = nw * 32 + nt * 8 + tg * 2;
        const float r0 = rnorm_s[col], r1 = rnorm_s[col + 1];
        acc[nt][0] = acc[nt][0] * r0 + b0v;
        acc[nt][1] = acc[nt][1] * r1 + b0v;
        acc[nt][2] = acc[nt][2] * r0 + b1v;
        acc[nt][3] = acc[nt][3] * r1 + b1v;
    }

    // per-column max
    float mA[4], mB[4];
#pragma unroll
    for (int nt = 0; nt < 4; nt++) {
        mA[nt] = fmaxf(acc[nt][0], acc[nt][2]);
        mB[nt] = fmaxf(acc[nt][1], acc[nt][3]);
    }
#pragma unroll
    for (int off = 4; off < 32; off <<= 1) {
#pragma unroll
        for (int nt = 0; nt < 4; nt++) {
            mA[nt] = fmaxf(mA[nt], __shfl_xor_sync(0xffffffffu, mA[nt], off));
            mB[nt] = fmaxf(mB[nt], __shfl_xor_sync(0xffffffffu, mB[nt], off));
        }
    }
    if (g == 0) {
#pragma unroll
        for (int nt = 0; nt < 4; nt++) {
            const int col = nw * 32 + nt * 8 + tg * 2;
            colmax4[col * 4 + mw] = mA[nt];
            colmax4[(col + 1) * 4 + mw] = mB[nt];
        }
    }
    __syncthreads();

    // exp + per-column sum
    float sA[4], sB[4];
#pragma unroll
    for (int nt = 0; nt < 4; nt++) {
        const int col = nw * 32 + nt * 8 + tg * 2;
        float4 c0 = *reinterpret_cast<float4*>(colmax4 + col * 4);
        float4 c1 = *reinterpret_cast<float4*>(colmax4 + (col + 1) * 4);
        float m0 = fmaxf(fmaxf(c0.x, c0.y), fmaxf(c0.z, c0.w));
        float m1 = fmaxf(fmaxf(c1.x, c1.y), fmaxf(c1.z, c1.w));
        acc[nt][0] = __expf(acc[nt][0] - m0);
        acc[nt][2] = __expf(acc[nt][2] - m0);
        acc[nt][1] = __expf(acc[nt][1] - m1);
        acc[nt][3] = __expf(acc[nt][3] - m1);
        sA[nt] = acc[nt][0] + acc[nt][2];
        sB[nt] = acc[nt][1] + acc[nt][3];
    }
#pragma unroll
    for (int off = 4; off < 32; off <<= 1) {
#pragma unroll
        for (int nt = 0; nt < 4; nt++) {
            sA[nt] += __shfl_xor_sync(0xffffffffu, sA[nt], off);
            sB[nt] += __shfl_xor_sync(0xffffffffu, sB[nt], off);
        }
    }
    if (g == 0) {
#pragma unroll
        for (int nt = 0; nt < 4; nt++) {
            const int col = nw * 32 + nt * 8 + tg * 2;
            colsum4[col * 4 + mw] = sA[nt];
            colsum4[(col + 1) * 4 + mw] = sB[nt];
        }
    }
    __syncthreads();

    // read all sums to regs first (Avs will overlay colsum region)
    float inv0[4], inv1[4];
#pragma unroll
    for (int nt = 0; nt < 4; nt++) {
        const int col = nw * 32 + nt * 8 + tg * 2;
        float4 s0 = *reinterpret_cast<float4*>(colsum4 + col * 4);
        float4 s1 = *reinterpret_cast<float4*>(colsum4 + (col + 1) * 4);
        inv0[nt] = 1.f / (s0.x + s0.y + s0.z + s0.w);
        inv1[nt] = 1.f / (s1.x + s1.y + s1.z + s1.w);
    }
    __syncthreads();

    // normalize; scatter into Avs[q=0..7][k][c_loc 0..15] (seg stride 24 u16 = 48 B);
    // also row sums for asum
    unsigned short* Avs = reinterpret_cast<unsigned short*>(sm + OFF_X);
    float rowsum = 0.f, rowsum8 = 0.f;
#pragma unroll
    for (int nt = 0; nt < 4; nt++) {
        const int cl = nw * 4 + nt;          // c_loc
        float a00 = acc[nt][0] * inv0[nt];   // (k=row,   q=2tg)
        float a01 = acc[nt][1] * inv1[nt];   // (k=row,   q=2tg+1)
        float a02 = acc[nt][2] * inv0[nt];   // (k=row+8, q=2tg)
        float a03 = acc[nt][3] * inv1[nt];   // (k=row+8, q=2tg+1)
        Avs[((2 * tg) * 64 + row) * 24 + cl]           = bf16bits(a00);
        Avs[((2 * tg + 1) * 64 + row) * 24 + cl]       = bf16bits(a01);
        Avs[((2 * tg) * 64 + row + 8) * 24 + cl]       = bf16bits(a02);
        Avs[((2 * tg + 1) * 64 + row + 8) * 24 + cl]   = bf16bits(a03);
        rowsum  += a00 + a01;
        rowsum8 += a02 + a03;
    }
#pragma unroll
    for (int off = 1; off < 4; off <<= 1) {
        rowsum  += __shfl_xor_sync(0xffffffffu, rowsum, off);
        rowsum8 += __shfl_xor_sync(0xffffffffu, rowsum8, off);
    }
    if (tg == 0) {
        asumW[row * 4 + nw] = rowsum;
        asumW[(row + 8) * 4 + nw] = rowsum8;
    }
    __syncthreads();

    // cooperative coalesced write of Av + asum partials
    {
        const unsigned* Avs32 = reinterpret_cast<const unsigned*>(sm + OFF_X);
        const int seg = t;                   // 0..511
        const int q = seg >> 6, k = seg & 63;
        uint4 v0 = *reinterpret_cast<const uint4*>(Avs32 + seg * 12);
        uint4 v1 = *reinterpret_cast<const uint4*>(Avs32 + seg * 12 + 4);
        size_t eo = ((((size_t)b * 8 + q) * 64 + k) * 512 + (size_t)tt * 16) >> 1;
        unsigned* dst = reinterpret_cast<unsigned*>(g_Av) + eo;
        *reinterpret_cast<uint4*>(dst) = v0;
        *reinterpret_cast<uint4*>(dst + 4) = v1;
    }
    if (t < KK)
        g_asum_part[(b * KK + t) * 32 + tt] =
            asumW[t * 4] + asumW[t * 4 + 1] + asumW[t * 4 + 2] + asumW[t * 4 + 3];

    __threadfence();
    __syncthreads();
    if (t == 0) atomicAdd(&g_flag[b], 1);

    // ================= PHASE 2: vlad GEMM over the SAME resident tile ==============
    if (t == 0) {
        int v;
        do {
            asm volatile("ld.acquire.gpu.global.s32 %0, [%1];"
                         : "=r"(v) : "l"(g_flag + b) : "memory");
            if (v < 32) __nanosleep(200);
        } while (v < 32);
    }
    __syncthreads();

#pragma unroll
    for (int nt = 0; nt < 4; nt++)
#pragma unroll
        for (int qd = 0; qd < 4; qd++) acc[nt][qd] = 0.f;

    const char* AvB = reinterpret_cast<const char*>(g_Av) +
                      (((size_t)b * 8 + qq) * 64) * 512 * 2;   // [k][c] bf16

    if (t < 256)
        cpasync16(smW + (t >> 2) * AST + (t & 3) * 4,
                  AvB + ((size_t)(t >> 2) * 512 + (t & 3) * 8) * 2);
    cp_commit();
    cp_wait0();
    __syncthreads();

    for (int it = 0; it < 16; it++) {
        const int c1 = (it + 1) * 32;
        const int s = it & 1, sn = s ^ 1;
        if (it < 15 && t < 256)
            cpasync16(smW + sn * (KK * AST) + (t >> 2) * AST + (t & 3) * 4,
                      AvB + ((size_t)(t >> 2) * 512 + c1 + (t & 3) * 8) * 2);
        cp_commit();

        const unsigned* As = smW + s * (KK * AST);
        const int rbase = it * 16;
#pragma unroll
        for (int ks = 0; ks < 2; ks++) {
            unsigned a[4];
            a[0] = As[row * AST + ks * 8 + tg];
            a[1] = As[(row + 8) * AST + ks * 8 + tg];
            a[2] = As[row * AST + ks * 8 + tg + 4];
            a[3] = As[(row + 8) * AST + ks * 8 + tg + 4];
#pragma unroll
            for (int nt = 0; nt < 4; nt++) {
                const int col = nw * 32 + nt * 8 + g;
                unsigned bf[2];
                bf[0] = T[(rbase + ks * 8 + tg) * BST + col];
                bf[1] = T[(rbase + ks * 8 + tg + 4) * BST + col];
                mma16816(acc[nt], a, bf);
            }
        }
        cp_wait0();
        __syncthreads();
    }

    // epilogue: scale by rnorm (column-wise) and write vpart[q][b][k][c2]
    float* vp = g_vpart + ((size_t)(qq * BB + b)) * KK * CC + r4 * 128;
#pragma unroll
    for (int nt = 0; nt < 4; nt++) {
        const int col = nw * 32 + nt * 8 + tg * 2;
        const float r0 = rnorm_s[col], r1 = rnorm_s[col + 1];
        *reinterpret_cast<float2*>(vp + (size_t)row * CC + col) =
            make_float2(acc[nt][0] * r0, acc[nt][1] * r1);
        *reinterpret_cast<float2*>(vp + (size_t)(row + 8) * CC + col) =
            make_float2(acc[nt][2] * r0, acc[nt][3] * r1);
    }
}

// ---------------- K4a: combine + intra-normalize ----------------
__global__ __launch_bounds__(128) void k_intra(const float* __restrict__ cent,
                                               float* __restrict__ out) {
    __shared__ float red[4];
    __shared__ float bcastA, bcastR;

    const int k = blockIdx.x, b = blockIdx.y;
    const int t = threadIdx.x;
    const int lane = t & 31, warp = t >> 5;

    if (warp == 0) {
        float s = g_asum_part[(b * KK + k) * 32 + lane];
#pragma unroll
        for (int o = 16; o > 0; o >>= 1) s += __shfl_down_sync(0xffffffffu, s, o);
        if (lane == 0) bcastA = s;
    }
    __syncthreads();
    const float as = bcastA;

    const size_t base = ((size_t)(b * KK + k)) * CC;
    const float4 cc = reinterpret_cast<const float4*>(cent + k * CC)[t];
    float4 v4 = make_float4(-as * cc.x, -as * cc.y, -as * cc.z, -as * cc.w);
#pragma unroll
    for (int s = 0; s < NSPLIT; s++) {
        const float4 a =
            reinterpret_cast<const float4*>(g_vpart + (size_t)s * BB * KK * CC + base)[t];
        v4.x += a.x; v4.y += a.y; v4.z += a.z; v4.w += a.w;
    }
    float ss = v4.x * v4.x + v4.y * v4.y + v4.z * v4.z + v4.w * v4.w;
#pragma unroll
    for (int o = 16; o > 0; o >>= 1) ss += __shfl_down_sync(0xffffffffu, ss, o);
    if (lane == 0) red[warp] = ss;
    __syncthreads();
    if (t == 0) {
        float tot = red[0] + red[1] + red[2] + red[3];
        float rinv = 1.f / fmaxf(sqrtf(tot), 1e-12f);
        bcastR = rinv;
        g_gss[b * KK + k] = tot * rinv * rinv;
    }
    __syncthreads();
    const float rinv = bcastR;
    float4 y;
    y.x = v4.x * rinv; y.y = v4.y * rinv; y.z = v4.z * rinv; y.w = v4.w * rinv;
    reinterpret_cast<float4*>(out + base)[t] = y;
}

// ---------------- K4b: global L2 normalize ----------------
__global__ __launch_bounds__(256) void k_gnorm(float* __restrict__ out) {
    __shared__ float red[8];
    __shared__ float bcast;
    const int b = blockIdx.x, t = threadIdx.x;
    const int lane = t & 31, warp = t >> 5;

    float s = (t < KK) ? g_gss[b * KK + t] : 0.f;
#pragma unroll
    for (int o = 16; o > 0; o >>= 1) s += __shfl_down_sync(0xffffffffu, s, o);
    if (lane == 0) red[warp] = s;
    __syncthreads();
    if (t == 0) {
        float tot = red[0] + red[1];
        bcast = 1.f / fmaxf(sqrtf(tot), 1e-12f);
    }
    __syncthreads();
    const float gr = bcast;
    float4* ob = reinterpret_cast<float4*>(out + (size_t)b * KK * CC);
#pragma unroll 4
    for (int u = t; u < KK * CC / 4; u += 256) {
        float4 v = ob[u];
        v.x *= gr; v.y *= gr; v.z *= gr; v.w *= gr;
        ob[u] = v;
    }
}

// ---------------- launch ----------------
extern "C" void kernel_launch(void* const* d_in, const int* in_sizes, int n_in,
                              void* d_out, int out_size) {
    (void)in_sizes; (void)n_in; (void)out_size;
    const float* x    = (const float*)d_in[0];
    const float* w    = (const float*)d_in[1];
    const float* bias = (const float*)d_in[2];
    const float* cent = (const float*)d_in[3];
    float* out = (float*)d_out;

    cudaFuncSetAttribute(k_main, cudaFuncAttributeMaxDynamicSharedMemorySize, SMEM_TOTAL);

    k_pre<<<128, 256>>>(w);
    k_main<<<BB * 32, 512, SMEM_TOTAL>>>(x, bias);
    k_intra<<<dim3(KK, BB), 128>>>(cent, out);
    k_gnorm<<<BB, 256>>>(out);
}

// round 14
// speedup vs baseline: 1.8046x; 1.8046x over previous
#include <cuda_runtime.h>
#include <cuda_bf16.h>
#include <math.h>

#define BB 64
#define CC 512
#define KK 64
#define HW 4096
#define NSPLIT 4

#define AST 20     // A tile row stride (u32): 64 rows x 16 kpairs
#define BST 136    // B tile row stride (u32): 16 kpair-rows x 128 cols

// ---- scratch (device globals; no allocation allowed) ----
__device__ __align__(16) __nv_bfloat16 g_wb[KK * CC];
__device__ __align__(16) float         g_rnorm[BB * HW];
__device__ __align__(16) __nv_bfloat16 g_assign[(size_t)BB * KK * HW];
__device__ __align__(16) float         g_asum_part[BB * KK * 32];
__device__ __align__(16) __nv_bfloat16 g_vpart[(size_t)NSPLIT * BB * KK * CC];
__device__ __align__(16) float         g_gss[BB * KK];

__device__ __forceinline__ void mma16816(float* d, const unsigned* a, const unsigned* b) {
    asm volatile(
        "mma.sync.aligned.m16n8k16.row.col.f32.bf16.bf16.f32 "
        "{%0,%1,%2,%3}, {%4,%5,%6,%7}, {%8,%9}, {%0,%1,%2,%3};"
        : "+f"(d[0]), "+f"(d[1]), "+f"(d[2]), "+f"(d[3])
        : "r"(a[0]), "r"(a[1]), "r"(a[2]), "r"(a[3]), "r"(b[0]), "r"(b[1]));
}

__device__ __forceinline__ unsigned pack_bf2(float lo, float hi) {
    __nv_bfloat162 p = __floats2bfloat162_rn(lo, hi);
    return *reinterpret_cast<unsigned*>(&p);
}

__device__ __forceinline__ void cpasync16(unsigned* smem, const void* gmem) {
    unsigned s = (unsigned)__cvta_generic_to_shared(smem);
    asm volatile("cp.async.ca.shared.global [%0], [%1], 16;\n" :: "r"(s), "l"(gmem));
}
__device__ __forceinline__ void cp_commit() {
    asm volatile("cp.async.commit_group;\n");
}
__device__ __forceinline__ void cp_wait0() {
    asm volatile("cp.async.wait_group 0;\n");
}

// ---------------- K_pre ----------------
__global__ void k_pre(const float* __restrict__ w) {
    int t = blockIdx.x * 256 + threadIdx.x;
    if (t < KK * CC) g_wb[t] = __float2bfloat16(w[t]);
}

// ---------------- K2: norm + logits GEMM + register softmax ----------------
// grid (HW/128, BB), 256 threads, K-chunk = 32 channels
__global__ __launch_bounds__(256) void k_logits(const float* __restrict__ x,
                                                const float* __restrict__ conv_b) {
    __shared__ __align__(16) unsigned smW[2 * KK * AST];
    __shared__ __align__(16) unsigned smX[2 * 16 * BST];
    __shared__ float rnorm_s[128];
    __shared__ float bias_s[KK];

    const int b  = blockIdx.y;
    const int bi = blockIdx.x;
    const int i0 = bi * 128;
    const int t  = threadIdx.x;
    const int lane = t & 31, warp = t >> 5;
    const int mw = warp >> 1, nw = warp & 1;
    const int g = lane >> 2, tg = lane & 3;

    if (t < KK) bias_s[t] = conv_b[t];

    const float* xb = x + (size_t)b * CC * HW + i0;
    const unsigned* wb32 = reinterpret_cast<const unsigned*>(g_wb);

    const int c4 = t & 31, cg = t >> 5;
    const int wrow = t >> 2, wq = t & 3;

    float acc[8][4];
#pragma unroll
    for (int nt = 0; nt < 8; nt++)
#pragma unroll
        for (int q = 0; q < 4; q++) acc[nt][q] = 0.f;
    float4 ssq4 = make_float4(0.f, 0.f, 0.f, 0.f);

    float4 xr[4];
    cpasync16(smW + wrow * AST + wq * 4, wb32 + wrow * (CC / 2) + wq * 4);
    cp_commit();
#pragma unroll
    for (int r = 0; r < 4; r++)
        xr[r] = *reinterpret_cast<const float4*>(xb + (size_t)(4 * cg + r) * HW + c4 * 4);
    {
        ssq4.x += xr[0].x * xr[0].x + xr[1].x * xr[1].x + xr[2].x * xr[2].x + xr[3].x * xr[3].x;
        ssq4.y += xr[0].y * xr[0].y + xr[1].y * xr[1].y + xr[2].y * xr[2].y + xr[3].y * xr[3].y;
        ssq4.z += xr[0].z * xr[0].z + xr[1].z * xr[1].z + xr[2].z * xr[2].z + xr[3].z * xr[3].z;
        ssq4.w += xr[0].w * xr[0].w + xr[1].w * xr[1].w + xr[2].w * xr[2].w + xr[3].w * xr[3].w;
        uint4 p0 = make_uint4(pack_bf2(xr[0].x, xr[1].x), pack_bf2(xr[0].y, xr[1].y),
                              pack_bf2(xr[0].z, xr[1].z), pack_bf2(xr[0].w, xr[1].w));
        uint4 p1 = make_uint4(pack_bf2(xr[2].x, xr[3].x), pack_bf2(xr[2].y, xr[3].y),
                              pack_bf2(xr[2].z, xr[3].z), pack_bf2(xr[2].w, xr[3].w));
        *reinterpret_cast<uint4*>(smX + (2 * cg) * BST + c4 * 4) = p0;
        *reinterpret_cast<uint4*>(smX + (2 * cg + 1) * BST + c4 * 4) = p1;
    }
    cp_wait0();
    __syncthreads();

    const int NIT = CC / 32;
    for (int it = 0; it < NIT; it++) {
        const int c1 = (it + 1) * 32;
        const int s = it & 1, sn = s ^ 1;
        if (it < NIT - 1) {
            cpasync16(smW + sn * (KK * AST) + wrow * AST + wq * 4,
                      wb32 + wrow * (CC / 2) + (c1 >> 1) + wq * 4);
            cp_commit();
#pragma unroll
            for (int r = 0; r < 4; r++)
                xr[r] = *reinterpret_cast<const float4*>(
                    xb + (size_t)(c1 + 4 * cg + r) * HW + c4 * 4);
        }

        const unsigned* Ws = smW + s * (KK * AST);
        const unsigned* Xs = smX + s * (16 * BST);
        const int row = mw * 16 + g;
#pragma unroll
        for (int ks = 0; ks < 2; ks++) {
            unsigned a[4];
            a[0] = Ws[row * AST + ks * 8 + tg];
            a[1] = Ws[(row + 8) * AST + ks * 8 + tg];
            a[2] = Ws[row * AST + ks * 8 + tg + 4];
            a[3] = Ws[(row + 8) * AST + ks * 8 + tg + 4];
#pragma unroll
            for (int nt = 0; nt < 8; nt++) {
                const int col = nw * 64 + nt * 8 + g;
                unsigned bf[2];
                bf[0] = Xs[(ks * 8 + tg) * BST + col];
                bf[1] = Xs[(ks * 8 + tg + 4) * BST + col];
                mma16816(acc[nt], a, bf);
            }
        }

        if (it < NIT - 1) {
            unsigned* Xn = smX + sn * (16 * BST);
            ssq4.x += xr[0].x * xr[0].x + xr[1].x * xr[1].x + xr[2].x * xr[2].x + xr[3].x * xr[3].x;
            ssq4.y += xr[0].y * xr[0].y + xr[1].y * xr[1].y + xr[2].y * xr[2].y + xr[3].y * xr[3].y;
            ssq4.z += xr[0].z * xr[0].z + xr[1].z * xr[1].z + xr[2].z * xr[2].z + xr[3].z * xr[3].z;
            ssq4.w += xr[0].w * xr[0].w + xr[1].w * xr[1].w + xr[2].w * xr[2].w + xr[3].w * xr[3].w;
            uint4 p0 = make_uint4(pack_bf2(xr[0].x, xr[1].x), pack_bf2(xr[0].y, xr[1].y),
                                  pack_bf2(xr[0].z, xr[1].z), pack_bf2(xr[0].w, xr[1].w));
            uint4 p1 = make_uint4(pack_bf2(xr[2].x, xr[3].x), pack_bf2(xr[2].y, xr[3].y),
                                  pack_bf2(xr[2].z, xr[3].z), pack_bf2(xr[2].w, xr[3].w));
            *reinterpret_cast<uint4*>(Xn + (2 * cg) * BST + c4 * 4) = p0;
            *reinterpret_cast<uint4*>(Xn + (2 * cg + 1) * BST + c4 * 4) = p1;
        }
        cp_wait0();
        __syncthreads();
    }

    // ---- ssq -> rnorm ----
    float4* ssq_sm = reinterpret_cast<float4*>(smW);
    ssq_sm[cg * 32 + c4] = ssq4;
    __syncthreads();
    if (t < 32) {
        float4 s = ssq_sm[t];
#pragma unroll
        for (int r = 1; r < 8; r++) {
            float4 u = ssq_sm[r * 32 + t];
            s.x += u.x; s.y += u.y; s.z += u.z; s.w += u.w;
        }
        float4 rn;
        rn.x = 1.f / fmaxf(sqrtf(s.x), 1e-12f);
        rn.y = 1.f / fmaxf(sqrtf(s.y), 1e-12f);
        rn.z = 1.f / fmaxf(sqrtf(s.z), 1e-12f);
        rn.w = 1.f / fmaxf(sqrtf(s.w), 1e-12f);
        reinterpret_cast<float4*>(rnorm_s)[t] = rn;
        *reinterpret_cast<float4*>(g_rnorm + (size_t)b * HW + i0 + t * 4) = rn;
    }
    __syncthreads();

    float* colmax4 = reinterpret_cast<float*>(smX);
    float* colsum4 = reinterpret_cast<float*>(smX) + 512;
    float* asum2   = reinterpret_cast<float*>(smX) + 1024;

    const int row = mw * 16 + g;
    const float b0v = bias_s[row], b1v = bias_s[row + 8];

#pragma unroll
    for (int nt = 0; nt < 8; nt++) {
        const int col = nw * 64 + nt * 8 + tg * 2;
        const float r0 = rnorm_s[col], r1 = rnorm_s[col + 1];
        acc[nt][0] = acc[nt][0] * r0 + b0v;
        acc[nt][1] = acc[nt][1] * r1 + b0v;
        acc[nt][2] = acc[nt][2] * r0 + b1v;
        acc[nt][3] = acc[nt][3] * r1 + b1v;
    }

    float mA[8], mB[8];
#pragma unroll
    for (int nt = 0; nt < 8; nt++) {
        mA[nt] = fmaxf(acc[nt][0], acc[nt][2]);
        mB[nt] = fmaxf(acc[nt][1], acc[nt][3]);
    }
#pragma unroll
    for (int off = 4; off < 32; off <<= 1) {
#pragma unroll
        for (int nt = 0; nt < 8; nt++) {
            mA[nt] = fmaxf(mA[nt], __shfl_xor_sync(0xffffffffu, mA[nt], off));
            mB[nt] = fmaxf(mB[nt], __shfl_xor_sync(0xffffffffu, mB[nt], off));
        }
    }
    if (g == 0) {
#pragma unroll
        for (int nt = 0; nt < 8; nt++) {
            const int col = nw * 64 + nt * 8 + tg * 2;
            colmax4[col * 4 + mw] = mA[nt];
            colmax4[(col + 1) * 4 + mw] = mB[nt];
        }
    }
    __syncthreads();

    float sA[8], sB[8];
#pragma unroll
    for (int nt = 0; nt < 8; nt++) {
        const int col = nw * 64 + nt * 8 + tg * 2;
        float4 c0 = *reinterpret_cast<float4*>(colmax4 + col * 4);
        float4 c1 = *reinterpret_cast<float4*>(colmax4 + (col + 1) * 4);
        float m0 = fmaxf(fmaxf(c0.x, c0.y), fmaxf(c0.z, c0.w));
        float m1 = fmaxf(fmaxf(c1.x, c1.y), fmaxf(c1.z, c1.w));
        acc[nt][0] = __expf(acc[nt][0] - m0);
        acc[nt][2] = __expf(acc[nt][2] - m0);
        acc[nt][1] = __expf(acc[nt][1] - m1);
        acc[nt][3] = __expf(acc[nt][3] - m1);
        sA[nt] = acc[nt][0] + acc[nt][2];
        sB[nt] = acc[nt][1] + acc[nt][3];
    }
#pragma unroll
    for (int off = 4; off < 32; off <<= 1) {
#pragma unroll
        for (int nt = 0; nt < 8; nt++) {
            sA[nt] += __shfl_xor_sync(0xffffffffu, sA[nt], off);
            sB[nt] += __shfl_xor_sync(0xffffffffu, sB[nt], off);
        }
    }
    if (g == 0) {
#pragma unroll
        for (int nt = 0; nt < 8; nt++) {
            const int col = nw * 64 + nt * 8 + tg * 2;
            colsum4[col * 4 + mw] = sA[nt];
            colsum4[(col + 1) * 4 + mw] = sB[nt];
        }
    }
    __syncthreads();

    unsigned* asg = reinterpret_cast<unsigned*>(g_assign) + (size_t)(b * KK) * (HW / 2);
    float rowsum = 0.f, rowsum8 = 0.f;
#pragma unroll
    for (int nt = 0; nt < 8; nt++) {
        const int col = nw * 64 + nt * 8 + tg * 2;
        float4 s0 = *reinterpret_cast<float4*>(colsum4 + col * 4);
        float4 s1 = *reinterpret_cast<float4*>(colsum4 + (col + 1) * 4);
        float inv0 = 1.f / (s0.x + s0.y + s0.z + s0.w);
        float inv1 = 1.f / (s1.x + s1.y + s1.z + s1.w);
        float a00 = acc[nt][0] * inv0, a01 = acc[nt][1] * inv1;
        float a02 = acc[nt][2] * inv0, a03 = acc[nt][3] * inv1;
        asg[(size_t)row * (HW / 2) + (i0 + col) / 2]       = pack_bf2(a00, a01);
        asg[(size_t)(row + 8) * (HW / 2) + (i0 + col) / 2] = pack_bf2(a02, a03);
        rowsum  += a00 + a01;
        rowsum8 += a02 + a03;
    }
#pragma unroll
    for (int off = 1; off < 4; off <<= 1) {
        rowsum  += __shfl_xor_sync(0xffffffffu, rowsum, off);
        rowsum8 += __shfl_xor_sync(0xffffffffu, rowsum8, off);
    }
    if (tg == 0) {
        asum2[row * 2 + nw] = rowsum;
        asum2[(row + 8) * 2 + nw] = rowsum8;
    }
    __syncthreads();
    if (t < KK)
        g_asum_part[(b * KK + t) * 32 + bi] = asum2[t * 2] + asum2[t * 2 + 1];
}

// ---------------- K3: vlad GEMM (split-K over i, i-chunk 32) ----------------
// grid (4, NSPLIT, BB), 256 threads
__global__ __launch_bounds__(256) void k_vlad(const float* __restrict__ x) {
    __shared__ __align__(16) unsigned smA[2 * KK * AST];
    __shared__ __align__(16) unsigned smX[2 * 16 * BST];
    __shared__ __align__(16) float4 rn4[8 * 32];

    const int c2b = blockIdx.x * 128;
    const int split = blockIdx.y;
    const int b = blockIdx.z;
    const int t = threadIdx.x;
    const int lane = t & 31, warp = t >> 5;
    const int mw = warp >> 1, nw = warp & 1;
    const int g = lane >> 2, tg = lane & 3;

    {
        const int j8 = t >> 5, c4l = t & 31;
        rn4[t] = *reinterpret_cast<const float4*>(
            g_rnorm + (size_t)b * HW + j8 * 512 + c2b + c4l * 4);
    }

    const float* xb = x + (size_t)b * CC * HW;
    const unsigned* asg32 = reinterpret_cast<const unsigned*>(g_assign + (size_t)b * KK * HW);

    const int c4 = t & 31, ig = t >> 5;
    const int arow = t >> 2, aq = t & 3;

    float acc[8][4];
#pragma unroll
    for (int nt = 0; nt < 8; nt++)
#pragma unroll
        for (int q = 0; q < 4; q++) acc[nt][q] = 0.f;

    const int ibase0 = split * (HW / NSPLIT);

    float4 xr[4];
    cpasync16(smA + arow * AST + aq * 4, asg32 + arow * (HW / 2) + (ibase0 >> 1) + aq * 4);
    cp_commit();
#pragma unroll
    for (int r = 0; r < 4; r++)
        xr[r] = *reinterpret_cast<const float4*>(
            xb + (size_t)(ibase0 + 4 * ig + r) * 512 + c2b + c4 * 4);
    __syncthreads();
    {
        uint4 p0, p1;
        {
            float4 rA = rn4[((4 * ig + 0) & 7) * 32 + c4];
            float4 rB = rn4[((4 * ig + 1) & 7) * 32 + c4];
            p0 = make_uint4(pack_bf2(xr[0].x * rA.x, xr[1].x * rB.x),
                            pack_bf2(xr[0].y * rA.y, xr[1].y * rB.y),
                            pack_bf2(xr[0].z * rA.z, xr[1].z * rB.z),
                            pack_bf2(xr[0].w * rA.w, xr[1].w * rB.w));
        }
        {
            float4 rA = rn4[((4 * ig + 2) & 7) * 32 + c4];
            float4 rB = rn4[((4 * ig + 3) & 7) * 32 + c4];
            p1 = make_uint4(pack_bf2(xr[2].x * rA.x, xr[3].x * rB.x),
                            pack_bf2(xr[2].y * rA.y, xr[3].y * rB.y),
                            pack_bf2(xr[2].z * rA.z, xr[3].z * rB.z),
                            pack_bf2(xr[2].w * rA.w, xr[3].w * rB.w));
        }
        *reinterpret_cast<uint4*>(smX + (2 * ig) * BST + c4 * 4) = p0;
        *reinterpret_cast<uint4*>(smX + (2 * ig + 1) * BST + c4 * 4) = p1;
    }
    cp_wait0();
    __syncthreads();

    const int NIT = (HW / NSPLIT) / 32;
    for (int it = 0; it < NIT; it++) {
        const int ibn = ibase0 + (it + 1) * 32;
        const int s = it & 1, sn = s ^ 1;
        if (it < NIT - 1) {
            cpasync16(smA + sn * (KK * AST) + arow * AST + aq * 4,
                      asg32 + arow * (HW / 2) + (ibn >> 1) + aq * 4);
            cp_commit();
#pragma unroll
            for (int r = 0; r < 4; r++)
                xr[r] = *reinterpret_cast<const float4*>(
                    xb + (size_t)(ibn + 4 * ig + r) * 512 + c2b + c4 * 4);
        }

        const unsigned* As = smA + s * (KK * AST);
        const unsigned* Xs = smX + s * (16 * BST);
        const int row = mw * 16 + g;
#pragma unroll
        for (int ks = 0; ks < 2; ks++) {
            unsigned a[4];
            a[0] = As[row * AST + ks * 8 + tg];
            a[1] = As[(row + 8) * AST + ks * 8 + tg];
            a[2] = As[row * AST + ks * 8 + tg + 4];
            a[3] = As[(row + 8) * AST + ks * 8 + tg + 4];
#pragma unroll
            for (int nt = 0; nt < 8; nt++) {
                const int col = nw * 64 + nt * 8 + g;
                unsigned bf[2];
                bf[0] = Xs[(ks * 8 + tg) * BST + col];
                bf[1] = Xs[(ks * 8 + tg + 4) * BST + col];
                mma16816(acc[nt], a, bf);
            }
        }

        if (it < NIT - 1) {
            unsigned* Xn = smX + sn * (16 * BST);
            uint4 p0, p1;
            {
                float4 rA = rn4[((4 * ig + 0) & 7) * 32 + c4];
                float4 rB = rn4[((4 * ig + 1) & 7) * 32 + c4];
                p0 = make_uint4(pack_bf2(xr[0].x * rA.x, xr[1].x * rB.x),
                                pack_bf2(xr[0].y * rA.y, xr[1].y * rB.y),
                                pack_bf2(xr[0].z * rA.z, xr[1].z * rB.z),
                                pack_bf2(xr[0].w * rA.w, xr[1].w * rB.w));
            }
            {
                float4 rA = rn4[((4 * ig + 2) & 7) * 32 + c4];
                float4 rB = rn4[((4 * ig + 3) & 7) * 32 + c4];
                p1 = make_uint4(pack_bf2(xr[2].x * rA.x, xr[3].x * rB.x),
                                pack_bf2(xr[2].y * rA.y, xr[3].y * rB.y),
                                pack_bf2(xr[2].z * rA.z, xr[3].z * rB.z),
                                pack_bf2(xr[2].w * rA.w, xr[3].w * rB.w));
            }
            *reinterpret_cast<uint4*>(Xn + (2 * ig) * BST + c4 * 4) = p0;
            *reinterpret_cast<uint4*>(Xn + (2 * ig + 1) * BST + c4 * 4) = p1;
        }
        cp_wait0();
        __syncthreads();
    }

    // epilogue: write bf16 partials
    unsigned* vp = reinterpret_cast<unsigned*>(g_vpart) +
                   (((size_t)(split * BB + b)) * KK * CC >> 1);
#pragma unroll
    for (int nt = 0; nt < 8; nt++) {
        const int col = c2b + nw * 64 + nt * 8 + tg * 2;
        const int row = mw * 16 + g;
        vp[((size_t)row * CC + col) >> 1]       = pack_bf2(acc[nt][0], acc[nt][1]);
        vp[((size_t)(row + 8) * CC + col) >> 1] = pack_bf2(acc[nt][2], acc[nt][3]);
    }
}

// ---------------- K4a: combine + intra-normalize ----------------
__global__ __launch_bounds__(128) void k_intra(const float* __restrict__ cent,
                                               float* __restrict__ out) {
    __shared__ float red[4];
    __shared__ float bcastA, bcastR;

    const int k = blockIdx.x, b = blockIdx.y;
    const int t = threadIdx.x;
    const int lane = t & 31, warp = t >> 5;

    if (warp == 0) {
        float s = g_asum_part[(b * KK + k) * 32 + lane];
#pragma unroll
        for (int o = 16; o > 0; o >>= 1) s += __shfl_down_sync(0xffffffffu, s, o);
        if (lane == 0) bcastA = s;
    }
    __syncthreads();
    const float as = bcastA;

    const size_t base = ((size_t)(b * KK + k)) * CC;
    const float4 cc = reinterpret_cast<const float4*>(cent + k * CC)[t];
    float4 v4 = make_float4(-as * cc.x, -as * cc.y, -as * cc.z, -as * cc.w);
    const unsigned* vp32 = reinterpret_cast<const unsigned*>(g_vpart);
#pragma unroll
    for (int s = 0; s < NSPLIT; s++) {
        uint2 u = *reinterpret_cast<const uint2*>(
            vp32 + (((size_t)s * BB * KK * CC + base) >> 1) + t * 2);
        float2 f0 = __bfloat1622float2(*reinterpret_cast<__nv_bfloat162*>(&u.x));
        float2 f1 = __bfloat1622float2(*reinterpret_cast<__nv_bfloat162*>(&u.y));
        v4.x += f0.x; v4.y += f0.y; v4.z += f1.x; v4.w += f1.y;
    }
    float ss = v4.x * v4.x + v4.y * v4.y + v4.z * v4.z + v4.w * v4.w;
#pragma unroll
    for (int o = 16; o > 0; o >>= 1) ss += __shfl_down_sync(0xffffffffu, ss, o);
    if (lane == 0) red[warp] = ss;
    __syncthreads();
    if (t == 0) {
        float tot = red[0] + red[1] + red[2] + red[3];
        float rinv = 1.f / fmaxf(sqrtf(tot), 1e-12f);
        bcastR = rinv;
        g_gss[b * KK + k] = tot * rinv * rinv;
    }
    __syncthreads();
    const float rinv = bcastR;
    float4 y;
    y.x = v4.x * rinv; y.y = v4.y * rinv; y.z = v4.z * rinv; y.w = v4.w * rinv;
    reinterpret_cast<float4*>(out + base)[t] = y;
}

// ---------------- K4b: global L2 normalize (parallel slices) ----------------
// grid (8, BB), 256 threads; each block scales a 4096-float slice
__global__ __launch_bounds__(256) void k_gnorm(float* __restrict__ out) {
    __shared__ float red[2];
    __shared__ float bcast;
    const int sl = blockIdx.x, b = blockIdx.y, t = threadIdx.x;
    const int lane = t & 31, warp = t >> 5;

    if (t < KK) {
        float s = g_gss[b * KK + t];
#pragma unroll
        for (int o = 16; o > 0; o >>= 1) s += __shfl_down_sync(0xffffffffu, s, o);
        if (lane == 0) red[warp] = s;
    }
    __syncthreads();
    if (t == 0) bcast = 1.f / fmaxf(sqrtf(red[0] + red[1]), 1e-12f);
    __syncthreads();
    const float gr = bcast;

    float4* ob = reinterpret_cast<float4*>(out + (size_t)b * KK * CC + sl * 4096);
#pragma unroll
    for (int u = 0; u < 4; u++) {
        float4 v = ob[u * 256 + t];
        v.x *= gr; v.y *= gr; v.z *= gr; v.w *= gr;
        ob[u * 256 + t] = v;
    }
}

// ---------------- launch ----------------
extern "C" void kernel_launch(void* const* d_in, const int* in_sizes, int n_in,
                              void* d_out, int out_size) {
    (void)in_sizes; (void)n_in; (void)out_size;
    const float* x    = (const float*)d_in[0];
    const float* w    = (const float*)d_in[1];
    const float* bias = (const float*)d_in[2];
    const float* cent = (const float*)d_in[3];
    float* out = (float*)d_out;

    k_pre<<<128, 256>>>(w);
    k_logits<<<dim3(HW / 128, BB), 256>>>(x, bias);
    k_vlad<<<dim3(4, NSPLIT, BB), 256>>>(x);
    k_intra<<<dim3(KK, BB), 128>>>(cent, out);
    k_gnorm<<<dim3(8, BB), 256>>>(out);
}